// round 13
// baseline (speedup 1.0000x reference)
#include <cuda_runtime.h>
#include <cuda_bf16.h>
#include <mma.h>

using namespace nvcuda;
typedef __nv_bfloat16 bf16;

#define Bsz 1024
#define Hd  512
#define G4  2048
#define Tlen 256
#define NCTA 128
#define NTHR 256
#define SMEM_BYTES 73728

// ---------------- device scratch (no allocation allowed) ----------------
__device__ __align__(16) bf16 g_h1h[2][Bsz*Hd], g_h1l[2][Bsz*Hd];
__device__ __align__(16) bf16 g_h2h[2][Bsz*Hd], g_h2l[2][Bsz*Hd];
__device__ __align__(16) float g_c1[Bsz*Hd], g_c2[Bsz*Hd];
__device__ __align__(16) float g_hid[Bsz*256];
__device__ __align__(16) float g_x[Bsz*2];
__device__ __align__(16) float g_b1[G4], g_b2[G4], g_wx[G4*2];
__device__ __align__(16) bf16 g_W1h[G4*Hd],  g_W1l[G4*Hd];    // Whh1 (gate-interleaved)
__device__ __align__(16) bf16 g_W2ah[G4*Hd], g_W2al[G4*Hd];   // Wih2
__device__ __align__(16) bf16 g_W2bh[G4*Hd], g_W2bl[G4*Hd];   // Whh2
__device__ __align__(16) bf16 g_Woh[256*Hd], g_Wol[256*Hd];   // Wo1 (direct)

__device__ unsigned g_bcnt = 0;
__device__ volatile unsigned g_bgen = 0;

__device__ __forceinline__ void split2(float v, bf16& h, bf16& l){
    h = __float2bfloat16(v);
    l = __float2bfloat16(v - __bfloat162float(h));
}

__device__ __forceinline__ void gridbar(){
    __syncthreads();
    if (threadIdx.x == 0){
        unsigned gen = g_bgen;
        __threadfence();
        unsigned a = atomicAdd(&g_bcnt, 1u);
        if (a == NCTA-1u){
            g_bcnt = 0;
            __threadfence();
            g_bgen = gen + 1u;
        } else {
            while (g_bgen == gen) __nanosleep(64);
        }
        __threadfence();
    }
    __syncthreads();
}

// ---------------- prep: interleave + split weights ----------------
// gate-interleaved column order: n' = unit*4 + gate  (gate 0..3 = i,f,g,o)
__global__ void prepW(const float* __restrict__ Whh1, const float* __restrict__ Wih2,
                      const float* __restrict__ Whh2){
    int i = blockIdx.x*512 + threadIdx.x;      // 2048 x 512 = G4*Hd
    int np = i >> 9, k = i & 511;
    int unit = np >> 2, gate = np & 3;
    int src = (gate*Hd + unit)*Hd + k;
    split2(Whh1[src], g_W1h[i],  g_W1l[i]);
    split2(Wih2[src], g_W2ah[i], g_W2al[i]);
    split2(Whh2[src], g_W2bh[i], g_W2bl[i]);
}
__global__ void prepWo(const float* __restrict__ Wo1){
    int i = blockIdx.x*512 + threadIdx.x;      // 256 x 512 = 256*Hd
    split2(Wo1[i], g_Woh[i], g_Wol[i]);
}
__global__ void prepSmall(const float* __restrict__ Wih1,
                          const float* __restrict__ bih1, const float* __restrict__ bhh1,
                          const float* __restrict__ bih2, const float* __restrict__ bhh2){
    int i = blockIdx.x*256 + threadIdx.x;      // 8 x 256 = 2048
    int unit = i >> 2, gate = i & 3;
    int src = gate*Hd + unit;
    g_b1[i] = bih1[src] + bhh1[src];
    g_b2[i] = bih2[src] + bhh2[src];
    g_wx[i*2]   = Wih1[src*2];
    g_wx[i*2+1] = Wih1[src*2+1];
    g_x[i] = 0.f;                              // Bsz*2 == 2048
}

// ---------------- init projection: init = z @ W_proj^T + b_proj ----------------
__global__ void __launch_bounds__(256) projk(const float* __restrict__ zp,
                                             const float* __restrict__ zs,
                                             const float* __restrict__ zt,
                                             const float* __restrict__ Wp,
                                             const float* __restrict__ bp){
    __shared__ float Zs[64][65];
    __shared__ float Ws[32][65];
    int m0 = blockIdx.y*64, n0 = blockIdx.x*32;
    int tid = threadIdx.x;
    int cc = tid & 31, rr0 = (tid >> 5) * 8;
    float acc[8];
    #pragma unroll
    for(int j=0;j<8;j++) acc[j]=0.f;
    for(int k0=0;k0<256;k0+=64){
        for(int i=tid;i<64*64;i+=256){
            int r=i>>6, c=i&63; int k=k0+c; int b=m0+r;
            float v;
            if(k<64)        v = zp[b*64 + k];
            else if(k<128)  v = zs[b*64 + k-64];
            else            v = zt[b*128 + k-128];
            Zs[r][c]=v;
        }
        for(int i=tid;i<32*64;i+=256){
            int r=i>>6, c=i&63;
            Ws[r][c] = Wp[(n0+r)*256 + k0+c];
        }
        __syncthreads();
        for(int k=0;k<64;k++){
            float w = Ws[cc][k];
            #pragma unroll
            for(int j=0;j<8;j++) acc[j] += Zs[rr0+j][k]*w;
        }
        __syncthreads();
    }
    int n = n0 + cc;
    for(int j=0;j<8;j++){
        int b = m0 + rr0 + j;
        float v = acc[j] + bp[n];
        if(n < 512){
            bf16 hh, ll; split2(v, hh, ll);
            g_h1h[0][b*Hd+n]=hh; g_h1l[0][b*Hd+n]=ll;
            g_h2h[0][b*Hd+n]=hh; g_h2l[0][b*Hd+n]=ll;
        } else {
            g_c1[b*Hd + n-512] = v;
            g_c2[b*Hd + n-512] = v;
        }
    }
}

// ---------------- persistent decoder kernel ----------------
// Split-bf16 3-product MMA everywhere: acc += Ah*Bh + Ah*Bl + Al*Bh (fp32 acc)
__global__ void __launch_bounds__(NTHR,1) persk(const float* __restrict__ bo1,
                                                const float* __restrict__ Wo2,
                                                const float* __restrict__ bo2,
                                                float* __restrict__ out){
    extern __shared__ __align__(16) char sm[];
    bf16 (*As_h)[72] = (bf16(*)[72])(sm);
    bf16 (*As_l)[72] = (bf16(*)[72])(sm + 18432);
    bf16 (*Bs_h)[72] = (bf16(*)[72])(sm + 36864);
    bf16 (*Bs_l)[72] = (bf16(*)[72])(sm + 55296);
    float (*Cs)[132] = (float(*)[132])(sm);     // epilogue overlay: 128 x 132 x 4 = 67584 B

    const int tid = threadIdx.x;
    const int wid = tid >> 5, lane = tid & 31;
    const int cta = blockIdx.x;

    for (int t = 0; t < Tlen; t++){
        const int R = t & 1, W = 1 - R;

        // ===== phase A (lstm1) and phase B (lstm2) =====
        for (int mode = 0; mode < 2; mode++){
            const int m0 = (cta >> 4) * 128;
            const int n0 = (cta & 15) * 128;
            const int wm = wid >> 2, wn = wid & 3;   // 2 x 4 warp grid, 64x32 per warp

            wmma::fragment<wmma::accumulator,16,16,16,float> acc[4][2];
            #pragma unroll
            for(int i=0;i<4;i++)
                #pragma unroll
                for(int j=0;j<2;j++) wmma::fill_fragment(acc[i][j], 0.f);

            const int NP = mode ? 2 : 1;
            for (int p = 0; p < NP; p++){
                const bf16 *Ah, *Al, *Bh, *Bl;
                if (mode == 0){ Ah=g_h1h[R]; Al=g_h1l[R]; Bh=g_W1h;  Bl=g_W1l; }
                else if (p==0){ Ah=g_h1h[W]; Al=g_h1l[W]; Bh=g_W2ah; Bl=g_W2al; }
                else          { Ah=g_h2h[R]; Al=g_h2l[R]; Bh=g_W2bh; Bl=g_W2bl; }

                for (int kc = 0; kc < 8; kc++){
                    __syncthreads();
                    const int k0 = kc * 64;
                    #pragma unroll
                    for(int it=0; it<4; it++){
                        int i = it*NTHR + tid;          // 0..1023
                        int r = i >> 3, q = i & 7;
                        const uint4* g;
                        g = (const uint4*)(Ah + (m0+r)*512 + k0) + q; *(uint4*)&As_h[r][q*8] = *g;
                        g = (const uint4*)(Al + (m0+r)*512 + k0) + q; *(uint4*)&As_l[r][q*8] = *g;
                        g = (const uint4*)(Bh + (n0+r)*512 + k0) + q; *(uint4*)&Bs_h[r][q*8] = *g;
                        g = (const uint4*)(Bl + (n0+r)*512 + k0) + q; *(uint4*)&Bs_l[r][q*8] = *g;
                    }
                    __syncthreads();
                    #pragma unroll
                    for(int kk=0; kk<64; kk+=16){
                        wmma::fragment<wmma::matrix_a,16,16,16,bf16,wmma::row_major> ah[4], al[4];
                        wmma::fragment<wmma::matrix_b,16,16,16,bf16,wmma::col_major> bh[2], bl[2];
                        #pragma unroll
                        for(int i=0;i<4;i++){
                            wmma::load_matrix_sync(ah[i], &As_h[wm*64+i*16][kk], 72);
                            wmma::load_matrix_sync(al[i], &As_l[wm*64+i*16][kk], 72);
                        }
                        #pragma unroll
                        for(int j=0;j<2;j++){
                            wmma::load_matrix_sync(bh[j], &Bs_h[wn*32+j*16][kk], 72);
                            wmma::load_matrix_sync(bl[j], &Bs_l[wn*32+j*16][kk], 72);
                        }
                        #pragma unroll
                        for(int i=0;i<4;i++)
                            #pragma unroll
                            for(int j=0;j<2;j++){
                                wmma::mma_sync(acc[i][j], ah[i], bh[j], acc[i][j]);
                                wmma::mma_sync(acc[i][j], ah[i], bl[j], acc[i][j]);
                                wmma::mma_sync(acc[i][j], al[i], bh[j], acc[i][j]);
                            }
                    }
                }
            }
            __syncthreads();
            #pragma unroll
            for(int i=0;i<4;i++)
                #pragma unroll
                for(int j=0;j<2;j++)
                    wmma::store_matrix_sync(&Cs[wm*64+i*16][wn*32+j*16], acc[i][j], 132, wmma::mem_row_major);
            __syncthreads();

            {   // LSTM cell epilogue: 128 rows x 32 unit-quads
                float* cbuf       = (mode==0) ? g_c1 : g_c2;
                const float* bias = (mode==0) ? g_b1 : g_b2;
                bf16* oh = (mode==0) ? g_h1h[W] : g_h2h[W];
                bf16* ol = (mode==0) ? g_h1l[W] : g_h2l[W];
                for(int idx = tid; idx < 4096; idx += NTHR){
                    int r = idx >> 5, uu = idx & 31;
                    int b  = m0 + r;
                    int nb = n0 + uu*4;
                    float gi = Cs[r][uu*4+0] + bias[nb+0];
                    float gf = Cs[r][uu*4+1] + bias[nb+1];
                    float gg = Cs[r][uu*4+2] + bias[nb+2];
                    float go = Cs[r][uu*4+3] + bias[nb+3];
                    if(mode == 0){
                        float x0 = g_x[b*2], x1 = g_x[b*2+1];
                        gi += x0*g_wx[(nb+0)*2] + x1*g_wx[(nb+0)*2+1];
                        gf += x0*g_wx[(nb+1)*2] + x1*g_wx[(nb+1)*2+1];
                        gg += x0*g_wx[(nb+2)*2] + x1*g_wx[(nb+2)*2+1];
                        go += x0*g_wx[(nb+3)*2] + x1*g_wx[(nb+3)*2+1];
                    }
                    int ci = b*Hd + (n0 >> 2) + uu;
                    float co = cbuf[ci];
                    float si = 1.f/(1.f+expf(-gi));
                    float sf = 1.f/(1.f+expf(-gf));
                    float so = 1.f/(1.f+expf(-go));
                    float cn = sf*co + si*tanhf(gg);
                    cbuf[ci] = cn;
                    float h = so*tanhf(cn);
                    bf16 hh, ll; split2(h, hh, ll);
                    oh[ci] = hh; ol[ci] = ll;
                }
            }
            gridbar();
        }

        // ===== phase C: hid = relu(h2[W] @ Wo1^T + bo1), 64x32 tile per CTA =====
        {
            const int m0 = (cta >> 3) * 64;
            const int n0 = (cta & 7) * 32;
            const int wm = wid >> 1, wn = wid & 1;   // 4 x 2 warp grid, one 16x16 frag each
            wmma::fragment<wmma::accumulator,16,16,16,float> acc;
            wmma::fill_fragment(acc, 0.f);
            const bf16 *Ah = g_h2h[W], *Al = g_h2l[W];

            for (int kc = 0; kc < 8; kc++){
                __syncthreads();
                const int k0 = kc * 64;
                #pragma unroll
                for(int it=0; it<2; it++){
                    int i = it*NTHR + tid;           // 0..511, rows 0..63
                    int r = i >> 3, q = i & 7;
                    const uint4* g;
                    g = (const uint4*)(Ah + (m0+r)*512 + k0) + q; *(uint4*)&As_h[r][q*8] = *g;
                    g = (const uint4*)(Al + (m0+r)*512 + k0) + q; *(uint4*)&As_l[r][q*8] = *g;
                }
                {
                    int i = tid;                     // 0..255, rows 0..31
                    int r = i >> 3, q = i & 7;
                    const uint4* g;
                    g = (const uint4*)(g_Woh + (n0+r)*512 + k0) + q; *(uint4*)&Bs_h[r][q*8] = *g;
                    g = (const uint4*)(g_Wol + (n0+r)*512 + k0) + q; *(uint4*)&Bs_l[r][q*8] = *g;
                }
                __syncthreads();
                #pragma unroll
                for(int kk=0; kk<64; kk+=16){
                    wmma::fragment<wmma::matrix_a,16,16,16,bf16,wmma::row_major> ah, al;
                    wmma::fragment<wmma::matrix_b,16,16,16,bf16,wmma::col_major> bh, bl;
                    wmma::load_matrix_sync(ah, &As_h[wm*16][kk], 72);
                    wmma::load_matrix_sync(al, &As_l[wm*16][kk], 72);
                    wmma::load_matrix_sync(bh, &Bs_h[wn*16][kk], 72);
                    wmma::load_matrix_sync(bl, &Bs_l[wn*16][kk], 72);
                    wmma::mma_sync(acc, ah, bh, acc);
                    wmma::mma_sync(acc, ah, bl, acc);
                    wmma::mma_sync(acc, al, bh, acc);
                }
            }
            __syncthreads();
            wmma::store_matrix_sync(&Cs[wm*16][wn*16], acc, 132, wmma::mem_row_major);
            __syncthreads();
            for(int idx = tid; idx < 2048; idx += NTHR){
                int r = idx >> 5, c = idx & 31;
                int n = n0 + c;
                float v = Cs[r][c] + bo1[n];
                g_hid[(m0+r)*256 + n] = v > 0.f ? v : 0.f;
            }
            gridbar();
        }

        // ===== phase D: y = hid @ Wo2^T + bo2 ; write out[:,t,:], feed x =====
        {
            int b = cta*8 + wid;                     // 128*8 = 1024 warps, one batch each
            const float* hid = g_hid + b*256;
            float a0 = 0.f, a1 = 0.f;
            #pragma unroll
            for(int k = lane; k < 256; k += 32){
                float v = hid[k];
                a0 += v * Wo2[k];
                a1 += v * Wo2[256 + k];
            }
            #pragma unroll
            for(int s=16; s; s>>=1){
                a0 += __shfl_xor_sync(0xffffffffu, a0, s);
                a1 += __shfl_xor_sync(0xffffffffu, a1, s);
            }
            if(lane == 0){
                a0 += bo2[0]; a1 += bo2[1];
                out[(b*Tlen + t)*2]     = a0;
                out[(b*Tlen + t)*2 + 1] = a1;
                g_x[b*2] = a0; g_x[b*2+1] = a1;
            }
            gridbar();
        }
    }
}

// ---------------- host ----------------
extern "C" void kernel_launch(void* const* d_in, const int* in_sizes, int n_in,
                              void* d_out, int out_size){
    const float* zp   = (const float*)d_in[0];
    const float* zs   = (const float*)d_in[1];
    const float* zt   = (const float*)d_in[2];
    const float* Wp   = (const float*)d_in[3];
    const float* bp   = (const float*)d_in[4];
    const float* Wih1 = (const float*)d_in[5];
    const float* Whh1 = (const float*)d_in[6];
    const float* bih1 = (const float*)d_in[7];
    const float* bhh1 = (const float*)d_in[8];
    const float* Wih2 = (const float*)d_in[9];
    const float* Whh2 = (const float*)d_in[10];
    const float* bih2 = (const float*)d_in[11];
    const float* bhh2 = (const float*)d_in[12];
    const float* Wo1  = (const float*)d_in[13];
    const float* bo1  = (const float*)d_in[14];
    const float* Wo2  = (const float*)d_in[15];
    const float* bo2  = (const float*)d_in[16];
    float* out = (float*)d_out;

    cudaFuncSetAttribute(persk, cudaFuncAttributeMaxDynamicSharedMemorySize, SMEM_BYTES);

    prepW<<<2048,512>>>(Whh1, Wih2, Whh2);
    prepWo<<<256,512>>>(Wo1);
    prepSmall<<<8,256>>>(Wih1, bih1, bhh1, bih2, bhh2);
    projk<<<dim3(32,16),256>>>(zp, zs, zt, Wp, bp);
    persk<<<NCTA, NTHR, SMEM_BYTES>>>(bo1, Wo2, bo2, out);
}

// round 15
// speedup vs baseline: 1.0025x; 1.0025x over previous
#include <cuda_runtime.h>
#include <cuda_bf16.h>
#include <mma.h>
#include <cstdint>

using namespace nvcuda;
typedef __nv_bfloat16 bf16;

#define Bsz 1024
#define Hd  512
#define G4  2048
#define Tlen 256
#define NCTA 128
#define NTHR 256
#define STAGE_BYTES 73728
#define DSMEM (2*STAGE_BYTES)

// ---------------- device scratch (no allocation allowed) ----------------
__device__ __align__(16) bf16 g_h1h[2][Bsz*Hd], g_h1l[2][Bsz*Hd];
__device__ __align__(16) bf16 g_h2h[2][Bsz*Hd], g_h2l[2][Bsz*Hd];
__device__ __align__(16) float g_c1[Bsz*Hd], g_c2[Bsz*Hd];
__device__ __align__(16) float g_hid[Bsz*256];
__device__ __align__(16) float g_x[Bsz*2];
__device__ __align__(16) float g_b1[G4], g_b2[G4], g_wx[G4*2];
__device__ __align__(16) bf16 g_W1h[G4*Hd],  g_W1l[G4*Hd];    // Whh1 (gate-interleaved)
__device__ __align__(16) bf16 g_W2ah[G4*Hd], g_W2al[G4*Hd];   // Wih2
__device__ __align__(16) bf16 g_W2bh[G4*Hd], g_W2bl[G4*Hd];   // Whh2
__device__ __align__(16) bf16 g_Woh[256*Hd], g_Wol[256*Hd];   // Wo1

__device__ unsigned g_bcnt = 0;
__device__ volatile unsigned g_bgen = 0;

// ---------------- helpers ----------------
__device__ __forceinline__ uint32_t smem_u32(const void* p){
    uint32_t a;
    asm("{ .reg .u64 t; cvta.to.shared.u64 t, %1; cvt.u32.u64 %0, t; }" : "=r"(a) : "l"(p));
    return a;
}
#define CP16(dst,src) asm volatile("cp.async.cg.shared.global [%0], [%1], 16;" :: "r"(dst), "l"(src) : "memory")
#define CP_COMMIT()   asm volatile("cp.async.commit_group;" ::: "memory")
#define CP_WAIT0()    asm volatile("cp.async.wait_group 0;" ::: "memory")
#define CP_WAIT1()    asm volatile("cp.async.wait_group 1;" ::: "memory")

__device__ __forceinline__ void split2(float v, bf16& h, bf16& l){
    h = __float2bfloat16(v);
    l = __float2bfloat16(v - __bfloat162float(h));
}
__device__ __forceinline__ void gridbar(){
    __syncthreads();
    if (threadIdx.x == 0){
        unsigned gen = g_bgen;
        __threadfence();
        unsigned a = atomicAdd(&g_bcnt, 1u);
        if (a == NCTA-1u){
            g_bcnt = 0;
            __threadfence();
            g_bgen = gen + 1u;
        } else {
            while (g_bgen == gen) __nanosleep(64);
        }
        __threadfence();
    }
    __syncthreads();
}

// chunk loader: ROWS rows x 64 cols bf16 -> smem tile (pitch 72 bf16 = 144 B)
template<int ROWS>
__device__ __forceinline__ void cpld(uint32_t dstbase, const bf16* g, int row0, int k0){
    int tid = threadIdx.x;
    #pragma unroll
    for(int it=0; it<ROWS/32; it++){
        int i = it*NTHR + tid;
        int r = i >> 3, q = i & 7;
        CP16(dstbase + (uint32_t)(r*144 + q*16),
             (const char*)(g + (size_t)(row0+r)*Hd + k0 + q*8));
    }
}

struct Pass { const bf16 *ah, *al, *bh, *bl; };

// ---------------- prep kernels (validated R13) ----------------
__global__ void prepW(const float* __restrict__ Whh1, const float* __restrict__ Wih2,
                      const float* __restrict__ Whh2){
    int i = blockIdx.x*512 + threadIdx.x;
    int np = i >> 9, k = i & 511;
    int unit = np >> 2, gate = np & 3;
    int src = (gate*Hd + unit)*Hd + k;
    split2(Whh1[src], g_W1h[i],  g_W1l[i]);
    split2(Wih2[src], g_W2ah[i], g_W2al[i]);
    split2(Whh2[src], g_W2bh[i], g_W2bl[i]);
}
__global__ void prepWo(const float* __restrict__ Wo1){
    int i = blockIdx.x*512 + threadIdx.x;
    split2(Wo1[i], g_Woh[i], g_Wol[i]);
}
__global__ void prepSmall(const float* __restrict__ Wih1,
                          const float* __restrict__ bih1, const float* __restrict__ bhh1,
                          const float* __restrict__ bih2, const float* __restrict__ bhh2){
    int i = blockIdx.x*256 + threadIdx.x;
    int unit = i >> 2, gate = i & 3;
    int src = gate*Hd + unit;
    g_b1[i] = bih1[src] + bhh1[src];
    g_b2[i] = bih2[src] + bhh2[src];
    g_wx[i*2]   = Wih1[src*2];
    g_wx[i*2+1] = Wih1[src*2+1];
    g_x[i] = 0.f;
}
__global__ void __launch_bounds__(256) projk(const float* __restrict__ zp,
                                             const float* __restrict__ zs,
                                             const float* __restrict__ zt,
                                             const float* __restrict__ Wp,
                                             const float* __restrict__ bp){
    __shared__ float Zs[64][65];
    __shared__ float Ws[32][65];
    int m0 = blockIdx.y*64, n0 = blockIdx.x*32;
    int tid = threadIdx.x;
    int cc = tid & 31, rr0 = (tid >> 5) * 8;
    float acc[8];
    #pragma unroll
    for(int j=0;j<8;j++) acc[j]=0.f;
    for(int k0=0;k0<256;k0+=64){
        for(int i=tid;i<64*64;i+=256){
            int r=i>>6, c=i&63; int k=k0+c; int b=m0+r;
            float v;
            if(k<64)        v = zp[b*64 + k];
            else if(k<128)  v = zs[b*64 + k-64];
            else            v = zt[b*128 + k-128];
            Zs[r][c]=v;
        }
        for(int i=tid;i<32*64;i+=256){
            int r=i>>6, c=i&63;
            Ws[r][c] = Wp[(n0+r)*256 + k0+c];
        }
        __syncthreads();
        for(int k=0;k<64;k++){
            float w = Ws[cc][k];
            #pragma unroll
            for(int j=0;j<8;j++) acc[j] += Zs[rr0+j][k]*w;
        }
        __syncthreads();
    }
    int n = n0 + cc;
    for(int j=0;j<8;j++){
        int b = m0 + rr0 + j;
        float v = acc[j] + bp[n];
        if(n < 512){
            bf16 hh, ll; split2(v, hh, ll);
            g_h1h[0][b*Hd+n]=hh; g_h1l[0][b*Hd+n]=ll;
            g_h2h[0][b*Hd+n]=hh; g_h2l[0][b*Hd+n]=ll;
        } else {
            g_c1[b*Hd + n-512] = v;
            g_c2[b*Hd + n-512] = v;
        }
    }
}

// ---------------- persistent decoder kernel ----------------
// Split-bf16 3-product MMA: acc += Ah*Bh + Ah*Bl + Al*Bh (fp32 acc)
// cp.async double-buffered k-chunk pipeline.
__global__ void __launch_bounds__(NTHR,1) persk(const float* __restrict__ bo1,
                                                const float* __restrict__ Wo2,
                                                const float* __restrict__ bo2,
                                                float* __restrict__ out){
    extern __shared__ __align__(16) char sm[];
    const uint32_t sb = smem_u32(sm);
    float (*Cs)[132] = (float(*)[132])(sm);     // epilogue overlay on stage 0 (67.6 KB)

    const int tid = threadIdx.x;
    const int wid = tid >> 5, lane = tid & 31;
    const int cta = blockIdx.x;

    for (int t = 0; t < Tlen; t++){
        const int R = t & 1, W = 1 - R;

        // ===== phases A (lstm1) and B (lstm2): 128x128 tiles =====
        for (int mode = 0; mode < 2; mode++){
            const int m0 = (cta >> 4) * 128;
            const int n0 = (cta & 15) * 128;
            const int wm = wid >> 2, wn = wid & 3;   // 2 x 4 warp grid, 64x32 per warp

            Pass ps[2];
            int NP;
            if (mode == 0){
                ps[0] = { g_h1h[R], g_h1l[R], g_W1h,  g_W1l };  NP = 1;
            } else {
                ps[0] = { g_h1h[W], g_h1l[W], g_W2ah, g_W2al };
                ps[1] = { g_h2h[R], g_h2l[R], g_W2bh, g_W2bl }; NP = 2;
            }
            const int NC = NP * 8;

            wmma::fragment<wmma::accumulator,16,16,16,float> acc[4][2];
            #pragma unroll
            for(int i=0;i<4;i++)
                #pragma unroll
                for(int j=0;j<2;j++) wmma::fill_fragment(acc[i][j], 0.f);

            // prologue: chunk 0 -> stage 0
            {
                uint32_t st = sb;
                cpld<128>(st,          ps[0].ah, m0, 0);
                cpld<128>(st + 18432u, ps[0].al, m0, 0);
                cpld<128>(st + 36864u, ps[0].bh, n0, 0);
                cpld<128>(st + 55296u, ps[0].bl, n0, 0);
                CP_COMMIT();
            }
            for (int cg = 0; cg < NC; cg++){
                const int s = cg & 1;
                __syncthreads();                     // stage s^1 readers done
                if (cg + 1 < NC){
                    const Pass& P = ps[(cg+1) >> 3];
                    const int k0 = ((cg+1) & 7) * 64;
                    uint32_t st = sb + (uint32_t)(s^1)*STAGE_BYTES;
                    cpld<128>(st,          P.ah, m0, k0);
                    cpld<128>(st + 18432u, P.al, m0, k0);
                    cpld<128>(st + 36864u, P.bh, n0, k0);
                    cpld<128>(st + 55296u, P.bl, n0, k0);
                    CP_COMMIT();
                    CP_WAIT1();
                } else {
                    CP_WAIT0();
                }
                __syncthreads();                     // chunk cg visible to all

                char* stc = sm + (size_t)s*STAGE_BYTES;
                bf16 (*As_h)[72] = (bf16(*)[72])(stc);
                bf16 (*As_l)[72] = (bf16(*)[72])(stc + 18432);
                bf16 (*Bs_h)[72] = (bf16(*)[72])(stc + 36864);
                bf16 (*Bs_l)[72] = (bf16(*)[72])(stc + 55296);

                #pragma unroll
                for(int kk=0; kk<64; kk+=16){
                    wmma::fragment<wmma::matrix_a,16,16,16,bf16,wmma::row_major> ah[4], al[4];
                    wmma::fragment<wmma::matrix_b,16,16,16,bf16,wmma::col_major> bh[2], bl[2];
                    #pragma unroll
                    for(int i=0;i<4;i++){
                        wmma::load_matrix_sync(ah[i], &As_h[wm*64+i*16][kk], 72);
                        wmma::load_matrix_sync(al[i], &As_l[wm*64+i*16][kk], 72);
                    }
                    #pragma unroll
                    for(int j=0;j<2;j++){
                        wmma::load_matrix_sync(bh[j], &Bs_h[wn*32+j*16][kk], 72);
                        wmma::load_matrix_sync(bl[j], &Bs_l[wn*32+j*16][kk], 72);
                    }
                    #pragma unroll
                    for(int i=0;i<4;i++)
                        #pragma unroll
                        for(int j=0;j<2;j++){
                            wmma::mma_sync(acc[i][j], ah[i], bh[j], acc[i][j]);
                            wmma::mma_sync(acc[i][j], ah[i], bl[j], acc[i][j]);
                            wmma::mma_sync(acc[i][j], al[i], bh[j], acc[i][j]);
                        }
                }
            }
            __syncthreads();
            #pragma unroll
            for(int i=0;i<4;i++)
                #pragma unroll
                for(int j=0;j<2;j++)
                    wmma::store_matrix_sync(&Cs[wm*64+i*16][wn*32+j*16], acc[i][j], 132, wmma::mem_row_major);
            __syncthreads();

            {   // LSTM cell epilogue (validated R13)
                float* cbuf       = (mode==0) ? g_c1 : g_c2;
                const float* bias = (mode==0) ? g_b1 : g_b2;
                bf16* oh = (mode==0) ? g_h1h[W] : g_h2h[W];
                bf16* ol = (mode==0) ? g_h1l[W] : g_h2l[W];
                for(int idx = tid; idx < 4096; idx += NTHR){
                    int r = idx >> 5, uu = idx & 31;
                    int b  = m0 + r;
                    int nb = n0 + uu*4;
                    float gi = Cs[r][uu*4+0] + bias[nb+0];
                    float gf = Cs[r][uu*4+1] + bias[nb+1];
                    float gg = Cs[r][uu*4+2] + bias[nb+2];
                    float go = Cs[r][uu*4+3] + bias[nb+3];
                    if(mode == 0){
                        float x0 = g_x[b*2], x1 = g_x[b*2+1];
                        gi += x0*g_wx[(nb+0)*2] + x1*g_wx[(nb+0)*2+1];
                        gf += x0*g_wx[(nb+1)*2] + x1*g_wx[(nb+1)*2+1];
                        gg += x0*g_wx[(nb+2)*2] + x1*g_wx[(nb+2)*2+1];
                        go += x0*g_wx[(nb+3)*2] + x1*g_wx[(nb+3)*2+1];
                    }
                    int ci = b*Hd + (n0 >> 2) + uu;
                    float co = cbuf[ci];
                    float si = 1.f/(1.f+expf(-gi));
                    float sf = 1.f/(1.f+expf(-gf));
                    float so = 1.f/(1.f+expf(-go));
                    float cn = sf*co + si*tanhf(gg);
                    cbuf[ci] = cn;
                    float h = so*tanhf(cn);
                    bf16 hh, ll; split2(h, hh, ll);
                    oh[ci] = hh; ol[ci] = ll;
                }
            }
            gridbar();
        }

        // ===== phase C: hid = relu(h2[W] @ Wo1^T + bo1), 64x32 tile per CTA =====
        {
            const int m0 = (cta >> 3) * 64;
            const int n0 = (cta & 7) * 32;
            const int wm = wid >> 1, wn = wid & 1;   // 4 x 2 warp grid
            wmma::fragment<wmma::accumulator,16,16,16,float> acc;
            wmma::fill_fragment(acc, 0.f);
            const bf16 *Ah = g_h2h[W], *Al = g_h2l[W];

            {
                uint32_t st = sb;
                cpld<64>(st,          Ah,    m0, 0);
                cpld<64>(st + 18432u, Al,    m0, 0);
                cpld<32>(st + 36864u, g_Woh, n0, 0);
                cpld<32>(st + 55296u, g_Wol, n0, 0);
                CP_COMMIT();
            }
            for (int cg = 0; cg < 8; cg++){
                const int s = cg & 1;
                __syncthreads();
                if (cg + 1 < 8){
                    const int k0 = (cg+1) * 64;
                    uint32_t st = sb + (uint32_t)(s^1)*STAGE_BYTES;
                    cpld<64>(st,          Ah,    m0, k0);
                    cpld<64>(st + 18432u, Al,    m0, k0);
                    cpld<32>(st + 36864u, g_Woh, n0, k0);
                    cpld<32>(st + 55296u, g_Wol, n0, k0);
                    CP_COMMIT();
                    CP_WAIT1();
                } else {
                    CP_WAIT0();
                }
                __syncthreads();

                char* stc = sm + (size_t)s*STAGE_BYTES;
                bf16 (*As_h)[72] = (bf16(*)[72])(stc);
                bf16 (*As_l)[72] = (bf16(*)[72])(stc + 18432);
                bf16 (*Bs_h)[72] = (bf16(*)[72])(stc + 36864);
                bf16 (*Bs_l)[72] = (bf16(*)[72])(stc + 55296);

                #pragma unroll
                for(int kk=0; kk<64; kk+=16){
                    wmma::fragment<wmma::matrix_a,16,16,16,bf16,wmma::row_major> ah, al;
                    wmma::fragment<wmma::matrix_b,16,16,16,bf16,wmma::col_major> bh, bl;
                    wmma::load_matrix_sync(ah, &As_h[wm*16][kk], 72);
                    wmma::load_matrix_sync(al, &As_l[wm*16][kk], 72);
                    wmma::load_matrix_sync(bh, &Bs_h[wn*16][kk], 72);
                    wmma::load_matrix_sync(bl, &Bs_l[wn*16][kk], 72);
                    wmma::mma_sync(acc, ah, bh, acc);
                    wmma::mma_sync(acc, ah, bl, acc);
                    wmma::mma_sync(acc, al, bh, acc);
                }
            }
            __syncthreads();
            wmma::store_matrix_sync(&Cs[wm*16][wn*16], acc, 132, wmma::mem_row_major);
            __syncthreads();
            for(int idx = tid; idx < 2048; idx += NTHR){
                int r = idx >> 5, c = idx & 31;
                int n = n0 + c;
                float v = Cs[r][c] + bo1[n];
                g_hid[(m0+r)*256 + n] = v > 0.f ? v : 0.f;
            }
            gridbar();
        }

        // ===== phase D: y = hid @ Wo2^T + bo2 ; out[:,t,:], feed x =====
        {
            int b = cta*8 + wid;
            const float* hid = g_hid + b*256;
            float a0 = 0.f, a1 = 0.f;
            #pragma unroll
            for(int k = lane; k < 256; k += 32){
                float v = hid[k];
                a0 += v * Wo2[k];
                a1 += v * Wo2[256 + k];
            }
            #pragma unroll
            for(int s=16; s; s>>=1){
                a0 += __shfl_xor_sync(0xffffffffu, a0, s);
                a1 += __shfl_xor_sync(0xffffffffu, a1, s);
            }
            if(lane == 0){
                a0 += bo2[0]; a1 += bo2[1];
                out[(b*Tlen + t)*2]     = a0;
                out[(b*Tlen + t)*2 + 1] = a1;
                g_x[b*2] = a0; g_x[b*2+1] = a1;
            }
            gridbar();
        }
    }
}

// ---------------- host ----------------
extern "C" void kernel_launch(void* const* d_in, const int* in_sizes, int n_in,
                              void* d_out, int out_size){
    const float* zp   = (const float*)d_in[0];
    const float* zs   = (const float*)d_in[1];
    const float* zt   = (const float*)d_in[2];
    const float* Wp   = (const float*)d_in[3];
    const float* bp   = (const float*)d_in[4];
    const float* Wih1 = (const float*)d_in[5];
    const float* Whh1 = (const float*)d_in[6];
    const float* bih1 = (const float*)d_in[7];
    const float* bhh1 = (const float*)d_in[8];
    const float* Wih2 = (const float*)d_in[9];
    const float* Whh2 = (const float*)d_in[10];
    const float* bih2 = (const float*)d_in[11];
    const float* bhh2 = (const float*)d_in[12];
    const float* Wo1  = (const float*)d_in[13];
    const float* bo1  = (const float*)d_in[14];
    const float* Wo2  = (const float*)d_in[15];
    const float* bo2  = (const float*)d_in[16];
    float* out = (float*)d_out;

    cudaFuncSetAttribute(persk, cudaFuncAttributeMaxDynamicSharedMemorySize, DSMEM);

    prepW<<<2048,512>>>(Whh1, Wih2, Whh2);
    prepWo<<<256,512>>>(Wo1);
    prepSmall<<<8,256>>>(Wih1, bih1, bhh1, bih2, bhh2);
    projk<<<dim3(32,16),256>>>(zp, zs, zt, Wp, bp);
    persk<<<NCTA, NTHR, DSMEM>>>(bo1, Wo2, bo2, out);
}

// round 16
// speedup vs baseline: 1.8998x; 1.8950x over previous
#include <cuda_runtime.h>
#include <cuda_fp16.h>
#include <mma.h>
#include <cstdint>

using namespace nvcuda;
typedef __half hf;

#define Bsz 1024
#define Hd  512
#define G4  2048
#define Tlen 256
#define NCTA 128
#define NTHR 256
#define STAGE_BYTES 36864
#define DSMEM (2*STAGE_BYTES)

// ---------------- device scratch (no allocation allowed) ----------------
__device__ __align__(16) hf g_h1[2][Bsz*Hd], g_h2[2][Bsz*Hd];
__device__ __align__(16) float g_c1[Bsz*Hd], g_c2[Bsz*Hd];
__device__ __align__(16) float g_hid[Bsz*256];
__device__ __align__(16) float g_b1[G4], g_b2[G4], g_wx[G4*2];
__device__ __align__(16) hf g_W1[G4*Hd];     // Whh1 (gate-interleaved)
__device__ __align__(16) hf g_W2a[G4*Hd];    // Wih2
__device__ __align__(16) hf g_W2b[G4*Hd];    // Whh2
__device__ __align__(16) hf g_Wo[256*Hd];    // Wo1

__device__ unsigned g_bcnt = 0;
__device__ volatile unsigned g_bgen = 0;

// ---------------- helpers ----------------
__device__ __forceinline__ uint32_t smem_u32(const void* p){
    uint32_t a;
    asm("{ .reg .u64 t; cvta.to.shared.u64 t, %1; cvt.u32.u64 %0, t; }" : "=r"(a) : "l"(p));
    return a;
}
#define CP16(dst,src) asm volatile("cp.async.cg.shared.global [%0], [%1], 16;" :: "r"(dst), "l"(src) : "memory")
#define CP_COMMIT()   asm volatile("cp.async.commit_group;" ::: "memory")
#define CP_WAIT0()    asm volatile("cp.async.wait_group 0;" ::: "memory")
#define CP_WAIT1()    asm volatile("cp.async.wait_group 1;" ::: "memory")

__device__ __forceinline__ void gridbar(){
    __syncthreads();
    if (threadIdx.x == 0){
        unsigned gen = g_bgen;
        __threadfence();
        unsigned a = atomicAdd(&g_bcnt, 1u);
        if (a == NCTA-1u){
            g_bcnt = 0;
            __threadfence();
            g_bgen = gen + 1u;
        } else {
            while (g_bgen == gen) __nanosleep(64);
        }
        __threadfence();
    }
    __syncthreads();
}

// chunk loader: ROWS rows x 64 cols fp16 -> smem tile (pitch 72 hf = 144 B)
template<int ROWS>
__device__ __forceinline__ void cpld(uint32_t dstbase, const hf* g, int row0, int k0){
    int tid = threadIdx.x;
    #pragma unroll
    for(int it=0; it<ROWS/32; it++){
        int i = it*NTHR + tid;
        int r = i >> 3, q = i & 7;
        CP16(dstbase + (uint32_t)(r*144 + q*16),
             (const char*)(g + (size_t)(row0+r)*Hd + k0 + q*8));
    }
}

struct Pass { const hf *a, *b; };

// ---------------- prep kernels ----------------
// gate-interleaved column order: n' = unit*4 + gate  (gate 0..3 = i,f,g,o)
__global__ void prepW(const float* __restrict__ Whh1, const float* __restrict__ Wih2,
                      const float* __restrict__ Whh2){
    int i = blockIdx.x*512 + threadIdx.x;      // 2048 x 512 = G4*Hd
    int np = i >> 9, k = i & 511;
    int unit = np >> 2, gate = np & 3;
    int src = (gate*Hd + unit)*Hd + k;
    g_W1[i]  = __float2half(Whh1[src]);
    g_W2a[i] = __float2half(Wih2[src]);
    g_W2b[i] = __float2half(Whh2[src]);
}
__global__ void prepWo(const float* __restrict__ Wo1){
    int i = blockIdx.x*512 + threadIdx.x;      // 256 x 512
    g_Wo[i] = __float2half(Wo1[i]);
}
__global__ void prepSmall(const float* __restrict__ Wih1,
                          const float* __restrict__ bih1, const float* __restrict__ bhh1,
                          const float* __restrict__ bih2, const float* __restrict__ bhh2){
    int i = blockIdx.x*256 + threadIdx.x;      // 8 x 256 = 2048
    int unit = i >> 2, gate = i & 3;
    int src = gate*Hd + unit;
    g_b1[i] = bih1[src] + bhh1[src];
    g_b2[i] = bih2[src] + bhh2[src];
    g_wx[i*2]   = Wih1[src*2];
    g_wx[i*2+1] = Wih1[src*2+1];
}

// ---------------- init projection: init = z @ W_proj^T + b_proj ----------------
__global__ void __launch_bounds__(256) projk(const float* __restrict__ zp,
                                             const float* __restrict__ zs,
                                             const float* __restrict__ zt,
                                             const float* __restrict__ Wp,
                                             const float* __restrict__ bp){
    __shared__ float Zs[64][65];
    __shared__ float Ws[32][65];
    int m0 = blockIdx.y*64, n0 = blockIdx.x*32;
    int tid = threadIdx.x;
    int cc = tid & 31, rr0 = (tid >> 5) * 8;
    float acc[8];
    #pragma unroll
    for(int j=0;j<8;j++) acc[j]=0.f;
    for(int k0=0;k0<256;k0+=64){
        for(int i=tid;i<64*64;i+=256){
            int r=i>>6, c=i&63; int k=k0+c; int b=m0+r;
            float v;
            if(k<64)        v = zp[b*64 + k];
            else if(k<128)  v = zs[b*64 + k-64];
            else            v = zt[b*128 + k-128];
            Zs[r][c]=v;
        }
        for(int i=tid;i<32*64;i+=256){
            int r=i>>6, c=i&63;
            Ws[r][c] = Wp[(n0+r)*256 + k0+c];
        }
        __syncthreads();
        for(int k=0;k<64;k++){
            float w = Ws[cc][k];
            #pragma unroll
            for(int j=0;j<8;j++) acc[j] += Zs[rr0+j][k]*w;
        }
        __syncthreads();
    }
    int n = n0 + cc;
    for(int j=0;j<8;j++){
        int b = m0 + rr0 + j;
        float v = acc[j] + bp[n];
        if(n < 512){
            hf h = __float2half(v);
            g_h1[0][b*Hd+n]=h; g_h2[0][b*Hd+n]=h;
        } else {
            g_c1[b*Hd + n-512] = v;
            g_c2[b*Hd + n-512] = v;
        }
    }
}

// ---------------- persistent decoder kernel (plain fp16, fp32 accum) ----------------
__global__ void __launch_bounds__(NTHR,1) persk(const float* __restrict__ bo1,
                                                const float* __restrict__ Wo2,
                                                const float* __restrict__ bo2,
                                                float* __restrict__ out){
    extern __shared__ __align__(16) char sm[];
    __shared__ float s_x[128][2];
    const uint32_t sb = smem_u32(sm);
    float (*Cs)[132] = (float(*)[132])(sm);     // epilogue overlay (67.6 KB over both stages)

    const int tid = threadIdx.x;
    const int wid = tid >> 5, lane = tid & 31;
    const int cta = blockIdx.x;

    for (int t = 0; t < Tlen; t++){
        const int R = t & 1, W = 1 - R;

        // ===== phases A (lstm1) and B (lstm2): 128x128 tiles =====
        for (int mode = 0; mode < 2; mode++){
            const int m0 = (cta >> 4) * 128;
            const int n0 = (cta & 15) * 128;
            const int wm = wid >> 2, wn = wid & 3;   // 2 x 4 warp grid, 64x32 per warp

            Pass ps[2];
            int NP;
            if (mode == 0){
                ps[0] = { g_h1[R], g_W1 };                       NP = 1;
            } else {
                ps[0] = { g_h1[W], g_W2a };
                ps[1] = { g_h2[R], g_W2b };                      NP = 2;
            }
            const int NC = NP * 8;

            wmma::fragment<wmma::accumulator,16,16,16,float> acc[4][2];
            #pragma unroll
            for(int i=0;i<4;i++)
                #pragma unroll
                for(int j=0;j<2;j++) wmma::fill_fragment(acc[i][j], 0.f);

            // prologue: chunk 0 -> stage 0
            cpld<128>(sb,          ps[0].a, m0, 0);
            cpld<128>(sb + 18432u, ps[0].b, n0, 0);
            CP_COMMIT();

            // phase-D replacement: compute x = y_{t-1} for own rows; write out[:,t-1,:]
            if (mode == 0){
                int r2 = tid >> 1, c2 = tid & 1;     // 128 rows x 2 outputs
                if (t > 0){
                    const float* hid = g_hid + (size_t)(m0 + r2)*256;
                    const float* w   = Wo2 + c2*256;
                    float a = 0.f;
                    #pragma unroll 8
                    for(int k=0;k<256;k++) a += hid[k]*w[k];
                    a += bo2[c2];
                    s_x[r2][c2] = a;
                    if((cta & 15) == 0)
                        out[((size_t)(m0 + r2)*Tlen + (t-1))*2 + c2] = a;
                } else {
                    s_x[r2][c2] = 0.f;
                }
            }

            for (int cg = 0; cg < NC; cg++){
                const int s = cg & 1;
                __syncthreads();                     // stage s^1 readers done
                if (cg + 1 < NC){
                    const Pass& P = ps[(cg+1) >> 3];
                    const int k0 = ((cg+1) & 7) * 64;
                    uint32_t st = sb + (uint32_t)(s^1)*STAGE_BYTES;
                    cpld<128>(st,          P.a, m0, k0);
                    cpld<128>(st + 18432u, P.b, n0, k0);
                    CP_COMMIT();
                    CP_WAIT1();
                } else {
                    CP_WAIT0();
                }
                __syncthreads();                     // chunk cg visible

                char* stc = sm + (size_t)s*STAGE_BYTES;
                hf (*As)[72] = (hf(*)[72])(stc);
                hf (*Bs)[72] = (hf(*)[72])(stc + 18432);

                #pragma unroll
                for(int kk=0; kk<64; kk+=16){
                    wmma::fragment<wmma::matrix_a,16,16,16,hf,wmma::row_major> af[4];
                    wmma::fragment<wmma::matrix_b,16,16,16,hf,wmma::col_major> bf[2];
                    #pragma unroll
                    for(int i=0;i<4;i++)
                        wmma::load_matrix_sync(af[i], &As[wm*64+i*16][kk], 72);
                    #pragma unroll
                    for(int j=0;j<2;j++)
                        wmma::load_matrix_sync(bf[j], &Bs[wn*32+j*16][kk], 72);
                    #pragma unroll
                    for(int i=0;i<4;i++)
                        #pragma unroll
                        for(int j=0;j<2;j++)
                            wmma::mma_sync(acc[i][j], af[i], bf[j], acc[i][j]);
                }
            }
            __syncthreads();
            #pragma unroll
            for(int i=0;i<4;i++)
                #pragma unroll
                for(int j=0;j<2;j++)
                    wmma::store_matrix_sync(&Cs[wm*64+i*16][wn*32+j*16], acc[i][j], 132, wmma::mem_row_major);
            __syncthreads();

            {   // LSTM cell epilogue
                float* cbuf       = (mode==0) ? g_c1 : g_c2;
                const float* bias = (mode==0) ? g_b1 : g_b2;
                hf* oh = (mode==0) ? g_h1[W] : g_h2[W];
                for(int idx = tid; idx < 4096; idx += NTHR){
                    int r = idx >> 5, uu = idx & 31;
                    int b  = m0 + r;
                    int nb = n0 + uu*4;
                    float gi = Cs[r][uu*4+0] + bias[nb+0];
                    float gf = Cs[r][uu*4+1] + bias[nb+1];
                    float gg = Cs[r][uu*4+2] + bias[nb+2];
                    float go = Cs[r][uu*4+3] + bias[nb+3];
                    if(mode == 0){
                        float x0 = s_x[r][0], x1 = s_x[r][1];
                        gi += x0*g_wx[(nb+0)*2] + x1*g_wx[(nb+0)*2+1];
                        gf += x0*g_wx[(nb+1)*2] + x1*g_wx[(nb+1)*2+1];
                        gg += x0*g_wx[(nb+2)*2] + x1*g_wx[(nb+2)*2+1];
                        go += x0*g_wx[(nb+3)*2] + x1*g_wx[(nb+3)*2+1];
                    }
                    int ci = b*Hd + (n0 >> 2) + uu;
                    float co = cbuf[ci];
                    float si = 1.f/(1.f+expf(-gi));
                    float sf = 1.f/(1.f+expf(-gf));
                    float so = 1.f/(1.f+expf(-go));
                    float cn = sf*co + si*tanhf(gg);
                    cbuf[ci] = cn;
                    oh[ci] = __float2half(so*tanhf(cn));
                }
            }
            gridbar();
        }

        // ===== phase C: hid = relu(h2[W] @ Wo1^T + bo1), 64x32 tile per CTA =====
        {
            const int m0 = (cta >> 3) * 64;
            const int n0 = (cta & 7) * 32;
            const int wm = wid >> 1, wn = wid & 1;   // 4 x 2 warp grid
            wmma::fragment<wmma::accumulator,16,16,16,float> acc;
            wmma::fill_fragment(acc, 0.f);
            const hf *Ah = g_h2[W];

            cpld<64>(sb,          Ah,   m0, 0);
            cpld<32>(sb + 18432u, g_Wo, n0, 0);
            CP_COMMIT();
            for (int cg = 0; cg < 8; cg++){
                const int s = cg & 1;
                __syncthreads();
                if (cg + 1 < 8){
                    const int k0 = (cg+1) * 64;
                    uint32_t st = sb + (uint32_t)(s^1)*STAGE_BYTES;
                    cpld<64>(st,          Ah,   m0, k0);
                    cpld<32>(st + 18432u, g_Wo, n0, k0);
                    CP_COMMIT();
                    CP_WAIT1();
                } else {
                    CP_WAIT0();
                }
                __syncthreads();

                char* stc = sm + (size_t)s*STAGE_BYTES;
                hf (*As)[72] = (hf(*)[72])(stc);
                hf (*Bs)[72] = (hf(*)[72])(stc + 18432);

                #pragma unroll
                for(int kk=0; kk<64; kk+=16){
                    wmma::fragment<wmma::matrix_a,16,16,16,hf,wmma::row_major> af;
                    wmma::fragment<wmma::matrix_b,16,16,16,hf,wmma::col_major> bf;
                    wmma::load_matrix_sync(af, &As[wm*16][kk], 72);
                    wmma::load_matrix_sync(bf, &Bs[wn*16][kk], 72);
                    wmma::mma_sync(acc, af, bf, acc);
                }
            }
            __syncthreads();
            wmma::store_matrix_sync(&Cs[wm*16][wn*16], acc, 132, wmma::mem_row_major);
            __syncthreads();
            for(int idx = tid; idx < 2048; idx += NTHR){
                int r = idx >> 5, c = idx & 31;
                int n = n0 + c;
                float v = Cs[r][c] + bo1[n];
                g_hid[(size_t)(m0+r)*256 + n] = v > 0.f ? v : 0.f;
            }
            gridbar();
        }
    }

    // final output row t=255
    {
        int b = cta*8 + wid;
        const float* hid = g_hid + (size_t)b*256;
        float a0 = 0.f, a1 = 0.f;
        #pragma unroll
        for(int k = lane; k < 256; k += 32){
            float v = hid[k];
            a0 += v * Wo2[k];
            a1 += v * Wo2[256 + k];
        }
        #pragma unroll
        for(int s=16; s; s>>=1){
            a0 += __shfl_xor_sync(0xffffffffu, a0, s);
            a1 += __shfl_xor_sync(0xffffffffu, a1, s);
        }
        if(lane == 0){
            out[((size_t)b*Tlen + 255)*2]     = a0 + bo2[0];
            out[((size_t)b*Tlen + 255)*2 + 1] = a1 + bo2[1];
        }
    }
}

// ---------------- host ----------------
extern "C" void kernel_launch(void* const* d_in, const int* in_sizes, int n_in,
                              void* d_out, int out_size){
    const float* zp   = (const float*)d_in[0];
    const float* zs   = (const float*)d_in[1];
    const float* zt   = (const float*)d_in[2];
    const float* Wp   = (const float*)d_in[3];
    const float* bp   = (const float*)d_in[4];
    const float* Wih1 = (const float*)d_in[5];
    const float* Whh1 = (const float*)d_in[6];
    const float* bih1 = (const float*)d_in[7];
    const float* bhh1 = (const float*)d_in[8];
    const float* Wih2 = (const float*)d_in[9];
    const float* Whh2 = (const float*)d_in[10];
    const float* bih2 = (const float*)d_in[11];
    const float* bhh2 = (const float*)d_in[12];
    const float* Wo1  = (const float*)d_in[13];
    const float* bo1  = (const float*)d_in[14];
    const float* Wo2  = (const float*)d_in[15];
    const float* bo2  = (const float*)d_in[16];
    float* out = (float*)d_out;

    cudaFuncSetAttribute(persk, cudaFuncAttributeMaxDynamicSharedMemorySize, DSMEM);

    prepW<<<2048,512>>>(Whh1, Wih2, Whh2);
    prepWo<<<256,512>>>(Wo1);
    prepSmall<<<8,256>>>(Wih1, bih1, bhh1, bih2, bhh2);
    projk<<<dim3(32,16),256>>>(zp, zs, zt, Wp, bp);
    persk<<<NCTA, NTHR, DSMEM>>>(bo1, Wo2, bo2, out);
}

// round 17
// speedup vs baseline: 2.3334x; 1.2282x over previous
#include <cuda_runtime.h>
#include <cuda_fp16.h>
#include <mma.h>
#include <cstdint>

using namespace nvcuda;
typedef __half hf;

#define Bsz 1024
#define Hd  512
#define G4  2048
#define Tlen 256
#define NCTA 128
#define NTHR 256
#define PH   136                     // smem pitch in hf (272 B = 17*16B, conflict-free)
#define TILE_BYTES (128*PH*2)        // 34816
#define STAGE_BYTES (2*TILE_BYTES)   // 69632
#define DSMEM (2*STAGE_BYTES)        // 139264

// ---------------- device scratch (no allocation allowed) ----------------
__device__ __align__(16) hf g_h1[2][Bsz*Hd], g_h2[2][Bsz*Hd];
__device__ __align__(16) float g_c1[Bsz*Hd], g_c2[Bsz*Hd];
__device__ __align__(16) float g_y[Bsz*2];
__device__ __align__(16) float g_b1[G4], g_b2[G4], g_wx[G4*2];
__device__ __align__(16) hf g_W1[G4*Hd];     // Whh1 (gate-interleaved)
__device__ __align__(16) hf g_W2a[G4*Hd];    // Wih2
__device__ __align__(16) hf g_W2b[G4*Hd];    // Whh2
__device__ __align__(16) hf g_Wo[256*Hd];    // Wo1

__device__ unsigned g_bcnt = 0;
__device__ volatile unsigned g_bgen = 0;

// ---------------- helpers ----------------
__device__ __forceinline__ uint32_t smem_u32(const void* p){
    uint32_t a;
    asm("{ .reg .u64 t; cvta.to.shared.u64 t, %1; cvt.u32.u64 %0, t; }" : "=r"(a) : "l"(p));
    return a;
}
#define CP16(dst,src) asm volatile("cp.async.cg.shared.global [%0], [%1], 16;" :: "r"(dst), "l"(src) : "memory")
#define CP_COMMIT()   asm volatile("cp.async.commit_group;" ::: "memory")
#define CP_WAIT0()    asm volatile("cp.async.wait_group 0;" ::: "memory")
#define CP_WAIT1()    asm volatile("cp.async.wait_group 1;" ::: "memory")

__device__ __forceinline__ void gridbar(){
    __syncthreads();
    if (threadIdx.x == 0){
        unsigned gen = g_bgen;
        __threadfence();
        unsigned a = atomicAdd(&g_bcnt, 1u);
        if (a == NCTA-1u){
            g_bcnt = 0;
            __threadfence();
            g_bgen = gen + 1u;
        } else {
            while (g_bgen == gen) __nanosleep(64);
        }
        __threadfence();
    }
    __syncthreads();
}

// chunk loader: ROWS rows x 128 cols fp16 -> smem tile (pitch 272 B)
template<int ROWS>
__device__ __forceinline__ void cpld(uint32_t dstbase, const hf* g, int row0, int k0){
    int tid = threadIdx.x;
    #pragma unroll
    for(int it=0; it<ROWS/16; it++){
        int i = it*NTHR + tid;
        int r = i >> 4, q = i & 15;
        CP16(dstbase + (uint32_t)(r*272 + q*16),
             (const char*)(g + (size_t)(row0+r)*Hd + k0 + q*8));
    }
}

struct Pass { const hf *a, *b; };

// ---------------- prep kernels ----------------
// gate-interleaved column order: n' = unit*4 + gate  (gate 0..3 = i,f,g,o)
__global__ void prepW(const float* __restrict__ Whh1, const float* __restrict__ Wih2,
                      const float* __restrict__ Whh2){
    int i = blockIdx.x*512 + threadIdx.x;      // 2048 x 512 = G4*Hd
    int np = i >> 9, k = i & 511;
    int unit = np >> 2, gate = np & 3;
    int src = (gate*Hd + unit)*Hd + k;
    g_W1[i]  = __float2half(Whh1[src]);
    g_W2a[i] = __float2half(Wih2[src]);
    g_W2b[i] = __float2half(Whh2[src]);
}
__global__ void prepWo(const float* __restrict__ Wo1){
    int i = blockIdx.x*512 + threadIdx.x;      // 256 x 512
    g_Wo[i] = __float2half(Wo1[i]);
}
__global__ void prepSmall(const float* __restrict__ Wih1,
                          const float* __restrict__ bih1, const float* __restrict__ bhh1,
                          const float* __restrict__ bih2, const float* __restrict__ bhh2){
    int i = blockIdx.x*256 + threadIdx.x;      // 8 x 256 = 2048
    int unit = i >> 2, gate = i & 3;
    int src = gate*Hd + unit;
    g_b1[i] = bih1[src] + bhh1[src];
    g_b2[i] = bih2[src] + bhh2[src];
    g_wx[i*2]   = Wih1[src*2];
    g_wx[i*2+1] = Wih1[src*2+1];
}

// ---------------- init projection: init = z @ W_proj^T + b_proj ----------------
__global__ void __launch_bounds__(256) projk(const float* __restrict__ zp,
                                             const float* __restrict__ zs,
                                             const float* __restrict__ zt,
                                             const float* __restrict__ Wp,
                                             const float* __restrict__ bp){
    __shared__ float Zs[64][65];
    __shared__ float Ws[32][65];
    int m0 = blockIdx.y*64, n0 = blockIdx.x*32;
    int tid = threadIdx.x;
    int cc = tid & 31, rr0 = (tid >> 5) * 8;
    float acc[8];
    #pragma unroll
    for(int j=0;j<8;j++) acc[j]=0.f;
    for(int k0=0;k0<256;k0+=64){
        for(int i=tid;i<64*64;i+=256){
            int r=i>>6, c=i&63; int k=k0+c; int b=m0+r;
            float v;
            if(k<64)        v = zp[b*64 + k];
            else if(k<128)  v = zs[b*64 + k-64];
            else            v = zt[b*128 + k-128];
            Zs[r][c]=v;
        }
        for(int i=tid;i<32*64;i+=256){
            int r=i>>6, c=i&63;
            Ws[r][c] = Wp[(n0+r)*256 + k0+c];
        }
        __syncthreads();
        for(int k=0;k<64;k++){
            float w = Ws[cc][k];
            #pragma unroll
            for(int j=0;j<8;j++) acc[j] += Zs[rr0+j][k]*w;
        }
        __syncthreads();
    }
    int n = n0 + cc;
    for(int j=0;j<8;j++){
        int b = m0 + rr0 + j;
        float v = acc[j] + bp[n];
        if(n < 512){
            hf h = __float2half(v);
            g_h1[0][b*Hd+n]=h; g_h2[0][b*Hd+n]=h;
        } else {
            g_c1[b*Hd + n-512] = v;
            g_c2[b*Hd + n-512] = v;
        }
    }
}

// ---------------- persistent decoder kernel (fp16, fp32 accum) ----------------
__global__ void __launch_bounds__(NTHR,1) persk(const float* __restrict__ bo1,
                                                const float* __restrict__ Wo2,
                                                const float* __restrict__ bo2,
                                                float* __restrict__ out){
    extern __shared__ __align__(16) char sm[];
    __shared__ float s_x[128][2];
    const uint32_t sb = smem_u32(sm);
    float (*Cs)[132] = (float(*)[132])(sm);     // epilogue overlay

    const int tid = threadIdx.x;
    const int wid = tid >> 5, lane = tid & 31;
    const int cta = blockIdx.x;

    for (int t = 0; t < Tlen; t++){
        const int R = t & 1, W = 1 - R;

        // ===== phases A (lstm1) and B (lstm2): 128x128 tiles, K-chunks of 128 =====
        for (int mode = 0; mode < 2; mode++){
            const int m0 = (cta >> 4) * 128;
            const int n0 = (cta & 15) * 128;
            const int wm = wid >> 2, wn = wid & 3;   // 2 x 4 warp grid, 64x32 per warp

            Pass ps[2];
            int NC;
            if (mode == 0){
                ps[0] = { g_h1[R], g_W1 };  ps[1] = ps[0];      NC = 4;
            } else {
                ps[0] = { g_h1[W], g_W2a };
                ps[1] = { g_h2[R], g_W2b };                     NC = 8;
            }

            wmma::fragment<wmma::accumulator,16,16,16,float> acc[4][2];
            #pragma unroll
            for(int i=0;i<4;i++)
                #pragma unroll
                for(int j=0;j<2;j++) wmma::fill_fragment(acc[i][j], 0.f);

            // prologue: chunk 0 -> stage 0
            cpld<128>(sb,              ps[0].a, m0, 0);
            cpld<128>(sb + TILE_BYTES, ps[0].b, n0, 0);
            CP_COMMIT();

            if (mode == 0){
                // x = y_{t-1} (+ write out[:,t-1,:]) — g_y filled by phase C atomics
                int r2 = tid >> 1, c2 = tid & 1;
                float xv = 0.f;
                if (t > 0){
                    xv = g_y[(m0 + r2)*2 + c2] + bo2[c2];
                    if((cta & 15) == 0)
                        out[((size_t)(m0 + r2)*Tlen + (t-1))*2 + c2] = xv;
                }
                s_x[r2][c2] = xv;
            } else {
                // zero g_y for this step's phase-C accumulation (8 CTAs cover all 2048)
                if (cta < 8) g_y[cta*256 + tid] = 0.f;
            }

            for (int cg = 0; cg < NC; cg++){
                const int s = cg & 1;
                __syncthreads();                     // stage s^1 readers done
                if (cg + 1 < NC){
                    const Pass& P = ps[(mode==0) ? 0 : ((cg+1) >> 2)];
                    const int k0 = (mode==0) ? (cg+1)*128 : ((cg+1) & 3)*128;
                    uint32_t st = sb + (uint32_t)(s^1)*STAGE_BYTES;
                    cpld<128>(st,              P.a, m0, k0);
                    cpld<128>(st + TILE_BYTES, P.b, n0, k0);
                    CP_COMMIT();
                    CP_WAIT1();
                } else {
                    CP_WAIT0();
                }
                __syncthreads();                     // chunk cg visible

                char* stc = sm + (size_t)s*STAGE_BYTES;
                hf (*As)[PH] = (hf(*)[PH])(stc);
                hf (*Bs)[PH] = (hf(*)[PH])(stc + TILE_BYTES);

                #pragma unroll
                for(int kk=0; kk<128; kk+=16){
                    wmma::fragment<wmma::matrix_a,16,16,16,hf,wmma::row_major> af[4];
                    wmma::fragment<wmma::matrix_b,16,16,16,hf,wmma::col_major> bf[2];
                    #pragma unroll
                    for(int i=0;i<4;i++)
                        wmma::load_matrix_sync(af[i], &As[wm*64+i*16][kk], PH);
                    #pragma unroll
                    for(int j=0;j<2;j++)
                        wmma::load_matrix_sync(bf[j], &Bs[wn*32+j*16][kk], PH);
                    #pragma unroll
                    for(int i=0;i<4;i++)
                        #pragma unroll
                        for(int j=0;j<2;j++)
                            wmma::mma_sync(acc[i][j], af[i], bf[j], acc[i][j]);
                }
            }
            __syncthreads();
            #pragma unroll
            for(int i=0;i<4;i++)
                #pragma unroll
                for(int j=0;j<2;j++)
                    wmma::store_matrix_sync(&Cs[wm*64+i*16][wn*32+j*16], acc[i][j], 132, wmma::mem_row_major);
            __syncthreads();

            {   // LSTM cell epilogue
                float* cbuf       = (mode==0) ? g_c1 : g_c2;
                const float* bias = (mode==0) ? g_b1 : g_b2;
                hf* oh = (mode==0) ? g_h1[W] : g_h2[W];
                for(int idx = tid; idx < 4096; idx += NTHR){
                    int r = idx >> 5, uu = idx & 31;
                    int b  = m0 + r;
                    int nb = n0 + uu*4;
                    float gi = Cs[r][uu*4+0] + bias[nb+0];
                    float gf = Cs[r][uu*4+1] + bias[nb+1];
                    float gg = Cs[r][uu*4+2] + bias[nb+2];
                    float go = Cs[r][uu*4+3] + bias[nb+3];
                    if(mode == 0){
                        float x0 = s_x[r][0], x1 = s_x[r][1];
                        gi += x0*g_wx[(nb+0)*2] + x1*g_wx[(nb+0)*2+1];
                        gf += x0*g_wx[(nb+1)*2] + x1*g_wx[(nb+1)*2+1];
                        gg += x0*g_wx[(nb+2)*2] + x1*g_wx[(nb+2)*2+1];
                        go += x0*g_wx[(nb+3)*2] + x1*g_wx[(nb+3)*2+1];
                    }
                    int ci = b*Hd + (n0 >> 2) + uu;
                    float co = cbuf[ci];
                    float si = 1.f/(1.f+expf(-gi));
                    float sf = 1.f/(1.f+expf(-gf));
                    float so = 1.f/(1.f+expf(-go));
                    float cn = sf*co + si*tanhf(gg);
                    cbuf[ci] = cn;
                    oh[ci] = __float2half(so*tanhf(cn));
                }
            }
            gridbar();
        }

        // ===== phase C: hid = relu(h2[W]@Wo1^T+bo1); y partials -> g_y atomics =====
        {
            const int m0 = (cta >> 3) * 64;
            const int n0 = (cta & 7) * 32;
            const int wm = wid >> 1, wn = wid & 1;   // 4 x 2 warp grid
            wmma::fragment<wmma::accumulator,16,16,16,float> acc;
            wmma::fill_fragment(acc, 0.f);
            const hf *Ah = g_h2[W];

            cpld<64>(sb,              Ah,   m0, 0);
            cpld<32>(sb + TILE_BYTES, g_Wo, n0, 0);
            CP_COMMIT();
            const float w20 = Wo2[n0 + lane];
            const float w21 = Wo2[256 + n0 + lane];
            const float b1v = bo1[n0 + lane];

            for (int cg = 0; cg < 4; cg++){
                const int s = cg & 1;
                __syncthreads();
                if (cg + 1 < 4){
                    const int k0 = (cg+1) * 128;
                    uint32_t st = sb + (uint32_t)(s^1)*STAGE_BYTES;
                    cpld<64>(st,              Ah,   m0, k0);
                    cpld<32>(st + TILE_BYTES, g_Wo, n0, k0);
                    CP_COMMIT();
                    CP_WAIT1();
                } else {
                    CP_WAIT0();
                }
                __syncthreads();

                char* stc = sm + (size_t)s*STAGE_BYTES;
                hf (*As)[PH] = (hf(*)[PH])(stc);
                hf (*Bs)[PH] = (hf(*)[PH])(stc + TILE_BYTES);

                #pragma unroll
                for(int kk=0; kk<128; kk+=16){
                    wmma::fragment<wmma::matrix_a,16,16,16,hf,wmma::row_major> af;
                    wmma::fragment<wmma::matrix_b,16,16,16,hf,wmma::col_major> bf;
                    wmma::load_matrix_sync(af, &As[wm*16][kk], PH);
                    wmma::load_matrix_sync(bf, &Bs[wn*16][kk], PH);
                    wmma::mma_sync(acc, af, bf, acc);
                }
            }
            __syncthreads();
            wmma::store_matrix_sync(&Cs[wm*16][wn*16], acc, 132, wmma::mem_row_major);
            __syncthreads();

            // y partial reduction: warp wid handles rows wid*8..wid*8+7
            #pragma unroll
            for(int rr=0; rr<8; rr++){
                int r = wid*8 + rr;
                float v = Cs[r][lane] + b1v;
                v = v > 0.f ? v : 0.f;
                float p0 = v * w20, p1 = v * w21;
                #pragma unroll
                for(int s2=16; s2; s2>>=1){
                    p0 += __shfl_xor_sync(0xffffffffu, p0, s2);
                    p1 += __shfl_xor_sync(0xffffffffu, p1, s2);
                }
                if(lane == 0){
                    atomicAdd(&g_y[(m0+r)*2],     p0);
                    atomicAdd(&g_y[(m0+r)*2 + 1], p1);
                }
            }
            gridbar();
        }
    }

    // final output row t=255 from g_y
    if (tid < 16){
        int i = cta*16 + tid;
        out[((size_t)(i >> 1)*Tlen + 255)*2 + (i & 1)] = g_y[i] + bo2[i & 1];
    }
}

// ---------------- host ----------------
extern "C" void kernel_launch(void* const* d_in, const int* in_sizes, int n_in,
                              void* d_out, int out_size){
    const float* zp   = (const float*)d_in[0];
    const float* zs   = (const float*)d_in[1];
    const float* zt   = (const float*)d_in[2];
    const float* Wp   = (const float*)d_in[3];
    const float* bp   = (const float*)d_in[4];
    const float* Wih1 = (const float*)d_in[5];
    const float* Whh1 = (const float*)d_in[6];
    const float* bih1 = (const float*)d_in[7];
    const float* bhh1 = (const float*)d_in[8];
    const float* Wih2 = (const float*)d_in[9];
    const float* Whh2 = (const float*)d_in[10];
    const float* bih2 = (const float*)d_in[11];
    const float* bhh2 = (const float*)d_in[12];
    const float* Wo1  = (const float*)d_in[13];
    const float* bo1  = (const float*)d_in[14];
    const float* Wo2  = (const float*)d_in[15];
    const float* bo2  = (const float*)d_in[16];
    float* out = (float*)d_out;

    cudaFuncSetAttribute(persk, cudaFuncAttributeMaxDynamicSharedMemorySize, DSMEM);

    prepW<<<2048,512>>>(Whh1, Wih2, Whh2);
    prepWo<<<256,512>>>(Wo1);
    prepSmall<<<8,256>>>(Wih1, bih1, bhh1, bih2, bhh2);
    projk<<<dim3(32,16),256>>>(zp, zs, zt, Wp, bp);
    persk<<<NCTA, NTHR, DSMEM>>>(bo1, Wo2, bo2, out);
}